// round 8
// baseline (speedup 1.0000x reference)
#include <cuda_runtime.h>
#include <cstdint>

#define B 64
#define K 8
#define V 128000
#define NCH 16
#define CH 8000           // V / NCH
#define PLACEHOLDER_F (-1.0f)

// scratch (no allocations allowed); zero-init at module load
__device__ int   g_acc[B * K];
__device__ float g_csum[B * NCH];
__device__ float g_cmax[B * NCH];
__device__ int   g_camax[B * NCH];
__device__ int   g_cnt[B];

// ---------------------------------------------------------------------------
// Kernel 1: 16 blocks x 32 threads, one (b,k) per thread.
// Each warp issues 32x3 independent scattered loads -> PTW/MLP fully overlapped.
// ---------------------------------------------------------------------------
__global__ void k1_accept(const int* __restrict__ dtok,
                          const float* __restrict__ dp,
                          const float* __restrict__ tp,
                          const float* __restrict__ us) {
    int i = blockIdx.x * 32 + threadIdx.x;   // 0 .. 511
    int tok = dtok[i];
    size_t off = (size_t)i * V + (size_t)tok;
    float p = __ldg(tp + off);
    float q = __ldg(dp + off);
    float u = us[i];
    float ap = fminf(1.0f, p / fmaxf(q, 1e-10f));
    g_acc[i] = (u < ap) ? 1 : 0;
}

// ---------------------------------------------------------------------------
// Kernel 2 (fused): grid (NCH, B), 256 thr.
//   - streams the j-row chunk: residual sum + target max/argmax
//   - c==0 block writes static output fields
//   - last block per batch finalizes: chunk cumsum, threshold search,
//     L2-hot re-read of crossing chunk, recovered token, counter reset
// ---------------------------------------------------------------------------
__global__ void __launch_bounds__(256) k2_fused(const int* __restrict__ dtok,
                                                const float* __restrict__ dp,
                                                const float* __restrict__ tp,
                                                const int* __restrict__ bonus,
                                                const float* __restrict__ us,
                                                float* __restrict__ out) {
    int c = blockIdx.x;          // chunk 0..15
    int b = blockIdx.y;          // batch 0..63
    int t = threadIdx.x;         // 256

    __shared__ int s_acc[K];
    __shared__ int s_na;
    if (t < K) s_acc[t] = g_acc[b * K + t];   // one L2-hot line
    __syncthreads();
    if (t == 0) {
        int na = 0;
        for (int i = 0; i < K; i++) { if (s_acc[i]) na++; else break; }
        s_na = na;
    }
    __syncthreads();
    int na = s_na;
    int j  = (na < K) ? na : (K - 1);

    // ---- streaming body ----
    size_t base = ((size_t)(b * K + j)) * V + (size_t)c * CH;
    const float4* t4 = (const float4*)(tp + base);
    const float4* d4 = (const float4*)(dp + base);

    float s = 0.0f;
    float mx = -1.0f;
    int   mi = V;
    const int N4 = CH / 4;       // 2000 -> ~8 iters/thread
    for (int i = t; i < N4; i += 256) {
        float4 tv = t4[i];
        float4 dv = d4[i];
        s += fmaxf(tv.x - dv.x, 0.0f);
        s += fmaxf(tv.y - dv.y, 0.0f);
        s += fmaxf(tv.z - dv.z, 0.0f);
        s += fmaxf(tv.w - dv.w, 0.0f);
        int gi = c * CH + i * 4;
        // strict > keeps first occurrence within the (increasing) thread walk
        if (tv.x > mx) { mx = tv.x; mi = gi; }
        if (tv.y > mx) { mx = tv.y; mi = gi + 1; }
        if (tv.z > mx) { mx = tv.z; mi = gi + 2; }
        if (tv.w > mx) { mx = tv.w; mi = gi + 3; }
    }

    __shared__ float ssum[256];
    __shared__ float smax[256];
    __shared__ int   sidx[256];
    ssum[t] = s; smax[t] = mx; sidx[t] = mi;
    __syncthreads();
    for (int st = 128; st > 0; st >>= 1) {
        if (t < st) {
            ssum[t] += ssum[t + st];
            float ov = smax[t + st]; int oi = sidx[t + st];
            if (ov > smax[t] || (ov == smax[t] && oi < sidx[t])) {
                smax[t] = ov; sidx[t] = oi;
            }
        }
        __syncthreads();
    }
    if (t == 0) {
        g_csum[b * NCH + c]  = ssum[0];
        g_cmax[b * NCH + c]  = smax[0];
        g_camax[b * NCH + c] = sidx[0];
    }

    // ---- static output fields (chunk-0 block) ----
    if (c == 0 && t == 0) {
        bool all = (na == K);
        for (int pos = 0; pos <= K; pos++) {
            if (pos < na) {
                out[b * (K + 1) + pos] = (float)dtok[b * K + pos];
            } else if (pos == na) {
                if (all) out[b * (K + 1) + pos] = (float)bonus[b];
                // else: finalizer writes the recovered token here
            } else {
                out[b * (K + 1) + pos] = PLACEHOLDER_F;
            }
        }
        int ob = B * (K + 1);
        out[ob + b]         = (float)na;          // num_accepted
        out[ob + B + b]     = (float)na;          // accepted_counts
        out[ob + 2 * B + b] = all ? 0.0f : 1.0f;  // recovered_counts
        out[ob + 3 * B + b] = all ? 1.0f : 0.0f;  // bonus_counts
    }

    // ---- last-block election ----
    __shared__ int s_last;
    if (t == 0) {
        __threadfence();
        int old = atomicAdd(&g_cnt[b], 1);
        s_last = (old == NCH - 1) ? 1 : 0;
    }
    __syncthreads();
    if (!s_last) return;

    // ---- finalize (one block per batch) ----
    __shared__ float cum[NCH];
    __shared__ float thr_s, pref_s, total_s;
    __shared__ int   cidx, fb_amax, cand;
    __shared__ float segsum[256];
    __shared__ float segex[256];

    if (t == 0) {
        g_cnt[b] = 0;   // reset for next graph replay
        float run = 0.0f;
        for (int ci = 0; ci < NCH; ci++) { run += g_csum[b * NCH + ci]; cum[ci] = run; }
        total_s = run;
        float thr = us[b * K + j] * run;
        thr_s = thr;
        int cc = NCH - 1;
        for (int i = 0; i < NCH; i++) if (cum[i] > thr) { cc = i; break; }
        cidx = cc;
        pref_s = (cc > 0) ? cum[cc - 1] : 0.0f;
        // fallback argmax(target row), first occurrence
        float fmx = -1.0f; int fmi = V;
        for (int ci = 0; ci < NCH; ci++) {
            float v = g_cmax[b * NCH + ci];
            int id  = g_camax[b * NCH + ci];
            if (v > fmx || (v == fmx && id < fmi)) { fmx = v; fmi = id; }
        }
        fb_amax = fmi;
        cand = V - 1;   // safety default (measure-zero boundary rounding)
    }
    __syncthreads();

    int cc = cidx;
    size_t fbase = ((size_t)(b * K + j)) * V + (size_t)cc * CH;

    // pass 1: per-thread segment sums (32 contiguous elems each; L2-hot re-read)
    const int SEG = CH / 256 + 1;   // 32 covers 8000 (31.25)
    int s0 = t * 32;
    float ls = 0.0f;
    for (int e = 0; e < 32; e++) {
        int ii = s0 + e;
        if (ii < CH) ls += fmaxf(tp[fbase + ii] - dp[fbase + ii], 0.0f);
    }
    segsum[t] = ls;
    __syncthreads();
    if (t == 0) {
        float run = pref_s;
        for (int i = 0; i < 256; i++) { segex[i] = run; run += segsum[i]; }
    }
    __syncthreads();

    // pass 2: locate crossing within this thread's segment (re-read, L2-hot)
    {
        float run = segex[t];
        float thr = thr_s;
        for (int e = 0; e < 32; e++) {
            int ii = s0 + e;
            if (ii >= CH) break;
            run += fmaxf(tp[fbase + ii] - dp[fbase + ii], 0.0f);
            if (run > thr) { atomicMin(&cand, cc * CH + ii); break; }
        }
    }
    __syncthreads();

    if (t == 0) {
        int rec = (total_s > 0.0f) ? cand : fb_amax;
        if (na < K) out[b * (K + 1) + na] = (float)rec;
    }
    (void)SEG;
}

// ---------------------------------------------------------------------------
extern "C" void kernel_launch(void* const* d_in, const int* in_sizes, int n_in,
                              void* d_out, int out_size) {
    const int*   dtok  = (const int*)d_in[0];   // [B,K]
    const float* dp    = (const float*)d_in[1]; // [B,K,V] draft probs
    const float* tp    = (const float*)d_in[2]; // [B,K,V] target probs
    const int*   bonus = (const int*)d_in[3];   // [B]
    const float* us    = (const float*)d_in[4]; // [B,K]
    float* out = (float*)d_out;

    k1_accept<<<16, 32>>>(dtok, dp, tp, us);
    dim3 g2(NCH, B);
    k2_fused<<<g2, 256>>>(dtok, dp, tp, bonus, us, out);
}

// round 9
// speedup vs baseline: 2.2334x; 2.2334x over previous
#include <cuda_runtime.h>
#include <cstdint>

#define B 64
#define K 8
#define V 128000
#define NCH 32
#define CH 4000           // V / NCH
#define PLACEHOLDER_F (-1.0f)

// scratch (no allocations allowed)
__device__ int   g_acc[B * K];
__device__ float g_csum[B * NCH];

// ---------------------------------------------------------------------------
// Kernel 1: 16 blocks x 32 threads, one (b,k) per thread; full-warp MLP.
// ---------------------------------------------------------------------------
__global__ void k1_accept(const int* __restrict__ dtok,
                          const float* __restrict__ dp,
                          const float* __restrict__ tp,
                          const float* __restrict__ us) {
    int i = blockIdx.x * 32 + threadIdx.x;   // 0 .. 511
    int tok = dtok[i];
    size_t off = (size_t)i * V + (size_t)tok;
    float p = __ldg(tp + off);
    float q = __ldg(dp + off);
    float u = us[i];
    float ap = fminf(1.0f, p / fmaxf(q, 1e-10f));
    g_acc[i] = (u < ap) ? 1 : 0;
}

// ---------------------------------------------------------------------------
// Kernel 2: grid (NCH, B), 256 thr. Pure streaming residual chunk sums.
//           c==0 block also writes all static output fields.
// ---------------------------------------------------------------------------
__global__ void __launch_bounds__(256) k2_chunks(const int* __restrict__ dtok,
                                                 const float* __restrict__ dp,
                                                 const float* __restrict__ tp,
                                                 const int* __restrict__ bonus,
                                                 float* __restrict__ out) {
    int c = blockIdx.x;          // chunk 0..NCH-1
    int b = blockIdx.y;          // batch 0..63
    int t = threadIdx.x;         // 256

    __shared__ int s_acc[K];
    __shared__ int s_na;
    if (t < K) s_acc[t] = g_acc[b * K + t];   // one L2-hot line
    __syncthreads();
    if (t == 0) {
        int na = 0;
        for (int i = 0; i < K; i++) { if (s_acc[i]) na++; else break; }
        s_na = na;
    }
    __syncthreads();
    int na = s_na;
    int j  = (na < K) ? na : (K - 1);

    size_t base = ((size_t)(b * K + j)) * V + (size_t)c * CH;
    const float4* t4 = (const float4*)(tp + base);
    const float4* d4 = (const float4*)(dp + base);

    float s = 0.0f;
    const int N4 = CH / 4;       // 1000 -> ~4 iters/thread
    #pragma unroll 4
    for (int i = t; i < N4; i += 256) {
        float4 tv = t4[i];
        float4 dv = d4[i];
        s += fmaxf(tv.x - dv.x, 0.0f);
        s += fmaxf(tv.y - dv.y, 0.0f);
        s += fmaxf(tv.z - dv.z, 0.0f);
        s += fmaxf(tv.w - dv.w, 0.0f);
    }

    // warp shuffle reduce, then cross-warp via smem
    for (int o = 16; o > 0; o >>= 1) s += __shfl_down_sync(0xffffffffu, s, o);
    __shared__ float wsum[8];
    if ((t & 31) == 0) wsum[t >> 5] = s;
    __syncthreads();
    if (t == 0) {
        float tot = 0.0f;
        #pragma unroll
        for (int w = 0; w < 8; w++) tot += wsum[w];
        g_csum[b * NCH + c] = tot;
    }

    // static output fields (chunk-0 block only)
    if (c == 0 && t == 0) {
        bool all = (na == K);
        for (int pos = 0; pos <= K; pos++) {
            if (pos < na) {
                out[b * (K + 1) + pos] = (float)dtok[b * K + pos];
            } else if (pos == na) {
                if (all) out[b * (K + 1) + pos] = (float)bonus[b];
                // else: k3 writes the recovered token here
            } else {
                out[b * (K + 1) + pos] = PLACEHOLDER_F;
            }
        }
        int ob = B * (K + 1);
        out[ob + b]         = (float)na;               // num_accepted
        out[ob + B + b]     = (float)na;               // accepted_counts
        out[ob + 2 * B + b] = all ? 0.0f : 1.0f;       // recovered_counts
        out[ob + 3 * B + b] = all ? 1.0f : 0.0f;       // bonus_counts
    }
}

// ---------------------------------------------------------------------------
// Kernel 3: one block per batch; chunk cumsum + threshold search + L2-hot
//           re-read of crossing chunk. Lazy full-row argmax only if total<=0.
// ---------------------------------------------------------------------------
__global__ void __launch_bounds__(256) k3_finalize(const float* __restrict__ dp,
                                                   const float* __restrict__ tp,
                                                   const float* __restrict__ us,
                                                   float* __restrict__ out) {
    int b = blockIdx.x;
    int t = threadIdx.x;   // 256

    __shared__ int s_acc[K];
    __shared__ float cum[NCH];
    __shared__ float thr_s, pref_s, total_s;
    __shared__ int   s_na, cidx, cand;
    __shared__ float segsum[256];
    __shared__ float segex[256];

    if (t < K) s_acc[t] = g_acc[b * K + t];
    __syncthreads();
    if (t == 0) {
        int na = 0;
        for (int i = 0; i < K; i++) { if (s_acc[i]) na++; else break; }
        s_na = na;
    }
    __syncthreads();
    int na = s_na;
    int j  = (na < K) ? na : (K - 1);
    size_t row = ((size_t)(b * K + j)) * V;

    if (t == 0) {
        float run = 0.0f;
        for (int ci = 0; ci < NCH; ci++) { run += g_csum[b * NCH + ci]; cum[ci] = run; }
        total_s = run;
        float thr = us[b * K + j] * run;
        thr_s = thr;
        int cc = NCH - 1;
        for (int i = 0; i < NCH; i++) if (cum[i] > thr) { cc = i; break; }
        cidx = cc;
        pref_s = (cc > 0) ? cum[cc - 1] : 0.0f;
        cand = V - 1;   // safety default (measure-zero boundary rounding)
    }
    __syncthreads();

    int rec;
    if (total_s > 0.0f) {
        int cc = cidx;
        size_t fbase = row + (size_t)cc * CH;

        // pass 1: per-thread contiguous segment sums (CH/256 = 15.6 -> 16 elems)
        const int SEG = (CH + 255) / 256;   // 16
        int s0 = t * SEG;
        float ls = 0.0f;
        #pragma unroll
        for (int e = 0; e < SEG; e++) {
            int ii = s0 + e;
            if (ii < CH) ls += fmaxf(tp[fbase + ii] - dp[fbase + ii], 0.0f);
        }
        segsum[t] = ls;
        __syncthreads();
        if (t == 0) {
            float run = pref_s;
            for (int i = 0; i < 256; i++) { segex[i] = run; run += segsum[i]; }
        }
        __syncthreads();

        // pass 2: locate crossing within segment (re-read, L2-hot)
        {
            float run = segex[t];
            float thr = thr_s;
            #pragma unroll
            for (int e = 0; e < SEG; e++) {
                int ii = s0 + e;
                if (ii >= CH) break;
                run += fmaxf(tp[fbase + ii] - dp[fbase + ii], 0.0f);
                if (run > thr) { atomicMin(&cand, cc * CH + ii); break; }
            }
        }
        __syncthreads();
        rec = cand;
    } else {
        // lazy fallback: full-row argmax of target (first occurrence) — never
        // taken on softmax inputs, kept for strict correctness
        __shared__ float amx[256];
        __shared__ int   ami[256];
        float mx = -1.0f; int mi = V;
        for (int i = t; i < V; i += 256) {
            float v = tp[row + i];
            if (v > mx) { mx = v; mi = i; }
        }
        amx[t] = mx; ami[t] = mi;
        __syncthreads();
        for (int st = 128; st > 0; st >>= 1) {
            if (t < st) {
                float ov = amx[t + st]; int oi = ami[t + st];
                if (ov > amx[t] || (ov == amx[t] && oi < ami[t])) {
                    amx[t] = ov; ami[t] = oi;
                }
            }
            __syncthreads();
        }
        rec = ami[0];
    }

    if (t == 0 && na < K) out[b * (K + 1) + na] = (float)rec;
}

// ---------------------------------------------------------------------------
extern "C" void kernel_launch(void* const* d_in, const int* in_sizes, int n_in,
                              void* d_out, int out_size) {
    const int*   dtok  = (const int*)d_in[0];   // [B,K]
    const float* dp    = (const float*)d_in[1]; // [B,K,V] draft probs
    const float* tp    = (const float*)d_in[2]; // [B,K,V] target probs
    const int*   bonus = (const int*)d_in[3];   // [B]
    const float* us    = (const float*)d_in[4]; // [B,K]
    float* out = (float*)d_out;

    k1_accept<<<16, 32>>>(dtok, dp, tp, us);
    dim3 g2(NCH, B);
    k2_chunks<<<g2, 256>>>(dtok, dp, tp, bonus, out);
    k3_finalize<<<B, 256>>>(dp, tp, us, out);
}